// round 15
// baseline (speedup 1.0000x reference)
#include <cuda_runtime.h>

// Problem constants (fixed by the dataset)
#define NN   50000
#define NE   800000
#define NG   64
#define NPAD 50048            // multiple of 128 for unguarded GEMM
#define NEG_SLOPE 0.01f
#define BN_EPS    1e-5f
#define NSB  196              // scan blocks: ceil(50000/256)

// ---------------- scratch (static __device__, no allocation) ----------------
__device__ __align__(16) float    g_bufA[NPAD * 256];
__device__ __align__(16) float    g_bufB[NPAD * 256];
__device__ __align__(16) unsigned g_Wh[256 * 256];
__device__ __align__(16) unsigned g_Wl[256 * 256];
__device__ __align__(16) int      g_csrsrc[NE];
__device__ __align__(16) int      g_rowptr[NN + 4];
__device__ __align__(16) int      g_deg[NN];
__device__ __align__(16) int      g_fill[NN];
__device__ __align__(16) float    g_dinv[NN];
__device__ __align__(16) float    g_selfnorm[NN];
__device__ __align__(16) int      g_blocksum[256];
__device__ __align__(16) int      g_blockoff[256];
__device__ __align__(16) float    g_colsum[256];
__device__ __align__(16) float    g_colsumsq[256];
__device__ __align__(16) float    g_alpha[256];
__device__ __align__(16) float    g_beta[256];
__device__ __align__(16) float    g_bconst[256];
__device__ __align__(16) float    g_pool[NG * 128];
__device__ __align__(16) int      g_counts[NG];

// ---------------- small utility kernels ----------------
__global__ void zero_misc_kernel() {
    int i = blockIdx.x * blockDim.x + threadIdx.x;
    if (i < NN) { g_deg[i] = 0; g_fill[i] = 0; }
    if (i < NG * 128) g_pool[i] = 0.f;
    if (i < NG) g_counts[i] = 0;
    if (blockIdx.x == 0) {               // fused BN-stat zeroing
        g_colsum[threadIdx.x] = 0.f;
        g_colsumsq[threadIdx.x] = 0.f;
    }
}

// edge_index is int32 (JAX x64 disabled downcasts int64 -> int32)
__global__ void deg_kernel(const int* __restrict__ ei) {
    int e = blockIdx.x * blockDim.x + threadIdx.x;
    if (e < NE) atomicAdd(&g_deg[ei[NE + e]], 1);  // dst row
}

// ---------------- parallel 3-stage exclusive scan of g_deg -> g_rowptr -----
__global__ void scan1_kernel() {
    __shared__ int sh[256];
    int b = blockIdx.x, t = threadIdx.x;
    int i = b * 256 + t;
    int v = (i < NN) ? g_deg[i] : 0;
    if (i < NN) {
        float d = (float)(v + 1);
        g_dinv[i] = rsqrtf(d);
        g_selfnorm[i] = 1.0f / d;
    }
    sh[t] = v;
    __syncthreads();
#pragma unroll
    for (int off = 1; off < 256; off <<= 1) {
        int add = (t >= off) ? sh[t - off] : 0;
        __syncthreads();
        sh[t] += add;
        __syncthreads();
    }
    if (i < NN) g_rowptr[i] = sh[t] - v;     // block-local exclusive
    if (t == 255) g_blocksum[b] = sh[255];
}

__global__ void scan2_kernel() {
    __shared__ int sh[256];
    int t = threadIdx.x;
    int v = (t < NSB) ? g_blocksum[t] : 0;
    sh[t] = v;
    __syncthreads();
#pragma unroll
    for (int off = 1; off < 256; off <<= 1) {
        int add = (t >= off) ? sh[t - off] : 0;
        __syncthreads();
        sh[t] += add;
        __syncthreads();
    }
    if (t < NSB) g_blockoff[t] = sh[t] - v;
}

__global__ void scan3_kernel() {
    int i = blockIdx.x * blockDim.x + threadIdx.x;
    if (i < NN) g_rowptr[i] += g_blockoff[i >> 8];
    if (i == 0) g_rowptr[NN] = NE;
}

__global__ void scatter_kernel(const int* __restrict__ ei) {
    int e = blockIdx.x * blockDim.x + threadIdx.x;
    if (e < NE) {
        int s = ei[e];
        int d = ei[NE + e];
        int p = g_rowptr[d] + atomicAdd(&g_fill[d], 1);
        g_csrsrc[p] = s;
    }
}

// ---------------- tf32 helpers ----------------
__device__ __forceinline__ unsigned f2tf(float v) {
    unsigned u;
    asm("cvt.rna.tf32.f32 %0, %1;" : "=r"(u) : "f"(v));
    return u;
}

__device__ __forceinline__ void mma8(float* c, const unsigned* a,
                                     unsigned b0, unsigned b1) {
    asm volatile(
        "mma.sync.aligned.m16n8k8.row.col.f32.tf32.tf32.f32 "
        "{%0,%1,%2,%3}, {%4,%5,%6,%7}, {%8,%9}, {%0,%1,%2,%3};\n"
        : "+f"(c[0]), "+f"(c[1]), "+f"(c[2]), "+f"(c[3])
        : "r"(a[0]), "r"(a[1]), "r"(a[2]), "r"(a[3]), "r"(b0), "r"(b1));
}

__device__ __forceinline__ void cp16(unsigned smem_addr, const void* gptr,
                                     unsigned srcbytes) {
    asm volatile("cp.async.ca.shared.global [%0], [%1], 16, %2;\n"
                 :: "r"(smem_addr), "l"(gptr), "r"(srcbytes));
}

// raw tf32 hi/lo split of W (layers whose BN is applied in the preceding agg)
__global__ void wsplit_kernel(const float* __restrict__ W, int count) {
    int i = blockIdx.x * 256 + threadIdx.x;
    if (i < count) {
        float w = W[i];
        unsigned h = f2tf(w);
        g_Wh[i] = h;
        g_Wl[i] = f2tf(w - __uint_as_float(h));
    }
}

// ---------------- 3xTF32 tensor-core GEMM (cp.async double-buffered) -------
// C[M,Nn] = A[M,K] @ W[K,Nn] + bias. W pre-split to (hi,lo) in global.
// FUSE=1: bias + LeakyReLU + BN-stat accumulation (rows < NN) in epilogue.
#define ASTRIDE 20                    // floats; 80B rows, conflict-free
#define BSTRIDE 136                   // words; 136%32==8 -> conflict-free
#define A_WORDS (128 * ASTRIDE)       // 2560
#define B_WORDS (16 * BSTRIDE)        // 2176
#define GEMM_SMEM_BYTES ((2 * A_WORDS + 4 * B_WORDS) * 4)   // 55296

template <int FUSE>
__global__ __launch_bounds__(256, 2)
void gemm_tf32_kernel(const float* __restrict__ A,
                      const unsigned* __restrict__ Wh,
                      const unsigned* __restrict__ Wl,
                      const float* __restrict__ bias, float* __restrict__ C,
                      int K, int Nn, int nrowsA) {
    extern __shared__ unsigned smem[];
    float* Af = (float*)smem;                      // [2][A_WORDS]
    unsigned* Bh = smem + 2 * A_WORDS;             // [2][B_WORDS]
    unsigned* Bl = Bh + 2 * B_WORDS;               // [2][B_WORDS]

    const int tid = threadIdx.x;
    const int lane = tid & 31;
    const int w = tid >> 5;
    const int wm = w >> 2;            // 0..1
    const int wn = w & 3;             // 0..3
    const int q = lane >> 2;          // 0..7
    const int r4 = lane & 3;          // 0..3

    const int rowbase = blockIdx.y * 128;
    const float* Ab = A + (size_t)rowbase * K;
    const int colbase = blockIdx.x * 128;
    float* Cb = C + (size_t)rowbase * Nn + colbase;

    unsigned af_base = (unsigned)__cvta_generic_to_shared(Af);
    unsigned bh_base = (unsigned)__cvta_generic_to_shared(Bh);
    unsigned bl_base = (unsigned)__cvta_generic_to_shared(Bl);

    auto issue = [&](int k0, int s) {
#pragma unroll
        for (int i = 0; i < 2; i++) {
            int idx = i * 256 + tid;
            int m = idx >> 2, ch = idx & 3;
            unsigned ok = (rowbase + m < nrowsA) ? 16u : 0u;
            const float* src = Ab + (size_t)m * K + k0 + ch * 4;
            cp16(af_base + (s * A_WORDS + m * ASTRIDE + ch * 4) * 4, src, ok);
        }
#pragma unroll
        for (int i = 0; i < 2; i++) {
            int idx = i * 256 + tid;
            int kk = idx >> 5, c = idx & 31;
            size_t goff = (size_t)(k0 + kk) * Nn + colbase + c * 4;
            unsigned soff = (s * B_WORDS + kk * BSTRIDE + c * 4) * 4;
            cp16(bh_base + soff, Wh + goff, 16u);
            cp16(bl_base + soff, Wl + goff, 16u);
        }
        asm volatile("cp.async.commit_group;\n" ::);
    };

    float acc[4][4][4];
#pragma unroll
    for (int mi = 0; mi < 4; mi++)
#pragma unroll
        for (int ni = 0; ni < 4; ni++)
#pragma unroll
            for (int rr = 0; rr < 4; rr++) acc[mi][ni][rr] = 0.f;

    const int T = K / 16;
    issue(0, 0);
    for (int t = 0; t < T; ++t) {
        const int p = t & 1;
        if (t + 1 < T) {
            issue((t + 1) * 16, (t + 1) & 1);
            asm volatile("cp.async.wait_group 1;\n" ::);
        } else {
            asm volatile("cp.async.wait_group 0;\n" ::);
        }
        __syncthreads();

        const float* Ap = Af + p * A_WORDS;
        const unsigned* Bhp = Bh + p * B_WORDS;
        const unsigned* Blp = Bl + p * B_WORDS;
#pragma unroll
        for (int ks = 0; ks < 2; ks++) {
            const int kk0 = ks * 8 + r4;
            unsigned ah[4][4], al[4][4];
#pragma unroll
            for (int mi = 0; mi < 4; mi++) {
                int m0 = wm * 64 + mi * 16 + q;
                float f0 = Ap[m0 * ASTRIDE + kk0];
                float f1 = Ap[(m0 + 8) * ASTRIDE + kk0];
                float f2 = Ap[m0 * ASTRIDE + kk0 + 4];
                float f3 = Ap[(m0 + 8) * ASTRIDE + kk0 + 4];
                ah[mi][0] = f2tf(f0); al[mi][0] = f2tf(f0 - __uint_as_float(ah[mi][0]));
                ah[mi][1] = f2tf(f1); al[mi][1] = f2tf(f1 - __uint_as_float(ah[mi][1]));
                ah[mi][2] = f2tf(f2); al[mi][2] = f2tf(f2 - __uint_as_float(ah[mi][2]));
                ah[mi][3] = f2tf(f3); al[mi][3] = f2tf(f3 - __uint_as_float(ah[mi][3]));
            }
#pragma unroll
            for (int ni = 0; ni < 4; ni++) {
                int n0b = wn * 32 + ni * 8 + q;
                unsigned bh0 = Bhp[kk0 * BSTRIDE + n0b];
                unsigned bh1 = Bhp[(kk0 + 4) * BSTRIDE + n0b];
                unsigned bl0 = Blp[kk0 * BSTRIDE + n0b];
                unsigned bl1 = Blp[(kk0 + 4) * BSTRIDE + n0b];
#pragma unroll
                for (int mi = 0; mi < 4; mi++) {
                    mma8(acc[mi][ni], ah[mi], bh0, bh1);  // hi*hi
                    mma8(acc[mi][ni], al[mi], bh0, bh1);  // lo*hi
                    mma8(acc[mi][ni], ah[mi], bl0, bl1);  // hi*lo
                }
            }
        }
        __syncthreads();
    }

    float* s_sum = (float*)smem;          // reuse smem post-loop
    float* s_sq = s_sum + 128;
    if (FUSE) {
        if (tid < 128) { s_sum[tid] = 0.f; s_sq[tid] = 0.f; }
        __syncthreads();
    }

#pragma unroll
    for (int ni = 0; ni < 4; ni++) {
        int ncol = wn * 32 + ni * 8 + 2 * r4;
        float bcx = bias[colbase + ncol];
        float bcy = bias[colbase + ncol + 1];
        float csx = 0.f, csy = 0.f, cqx = 0.f, cqy = 0.f;
#pragma unroll
        for (int mi = 0; mi < 4; mi++) {
            int row0 = wm * 64 + mi * 16 + q;
            float v0x = acc[mi][ni][0] + bcx, v0y = acc[mi][ni][1] + bcy;
            float v1x = acc[mi][ni][2] + bcx, v1y = acc[mi][ni][3] + bcy;
            if (FUSE) {
                v0x = (v0x > 0.f) ? v0x : NEG_SLOPE * v0x;
                v0y = (v0y > 0.f) ? v0y : NEG_SLOPE * v0y;
                v1x = (v1x > 0.f) ? v1x : NEG_SLOPE * v1x;
                v1y = (v1y > 0.f) ? v1y : NEG_SLOPE * v1y;
                if (rowbase + row0 < NN) {
                    csx += v0x; csy += v0y;
                    cqx = fmaf(v0x, v0x, cqx); cqy = fmaf(v0y, v0y, cqy);
                }
                if (rowbase + row0 + 8 < NN) {
                    csx += v1x; csy += v1y;
                    cqx = fmaf(v1x, v1x, cqx); cqy = fmaf(v1y, v1y, cqy);
                }
            }
            *(float2*)(Cb + (size_t)row0 * Nn + ncol) = make_float2(v0x, v0y);
            *(float2*)(Cb + (size_t)(row0 + 8) * Nn + ncol) = make_float2(v1x, v1y);
        }
        if (FUSE) {
            atomicAdd(&s_sum[ncol], csx);
            atomicAdd(&s_sum[ncol + 1], csy);
            atomicAdd(&s_sq[ncol], cqx);
            atomicAdd(&s_sq[ncol + 1], cqy);
        }
    }
    if (FUSE) {
        __syncthreads();
        if (tid < 128) {
            atomicAdd(&g_colsum[colbase + tid], s_sum[tid]);
            atomicAdd(&g_colsumsq[colbase + tid], s_sq[tid]);
        }
    }
}

// ---------------- pre-aggregation (SpMM): out = Â · val ---------------------
// val = USE_BN ? (a∘alpha + beta) : a, applied via the weight-sum identity:
// out = alpha∘(dn·acc + sn·a[n]) + (dn·ws + sn)·beta
template <int DO, int USE_BN>
__global__ void agg_pre_kernel(const float* __restrict__ hw,
                               float* __restrict__ out) {
    const int TX = DO / 4;
    const int TY = 256 / TX;
    const int NPB = 32;
    const int tx = threadIdx.x;
    const int ty = threadIdx.y;
    const float4* hw4 = (const float4*)hw;
    float4* out4 = (float4*)out;

    float4 al4, be4;
    if (USE_BN) {
        al4 = *(const float4*)(g_alpha + 4 * tx);
        be4 = *(const float4*)(g_beta + 4 * tx);
    }

    int n0 = blockIdx.x * NPB;
    int n1 = min(n0 + NPB, NN);

    for (int n = n0 + ty; n < n1; n += TY) {
        int e0 = g_rowptr[n], e1 = g_rowptr[n + 1];
        float4 acc = make_float4(0.f, 0.f, 0.f, 0.f);
        float ws = 0.f;
        int e = e0;
        for (; e + 4 <= e1; e += 4) {
            int i0 = g_csrsrc[e],     i1 = g_csrsrc[e + 1];
            int i2 = g_csrsrc[e + 2], i3 = g_csrsrc[e + 3];
            float w0 = g_dinv[i0], w1 = g_dinv[i1];
            float w2 = g_dinv[i2], w3 = g_dinv[i3];
            float4 v0 = hw4[(size_t)i0 * TX + tx];
            float4 v1 = hw4[(size_t)i1 * TX + tx];
            float4 v2 = hw4[(size_t)i2 * TX + tx];
            float4 v3 = hw4[(size_t)i3 * TX + tx];
            ws += (w0 + w1) + (w2 + w3);
            acc.x = fmaf(v0.x, w0, acc.x); acc.y = fmaf(v0.y, w0, acc.y);
            acc.z = fmaf(v0.z, w0, acc.z); acc.w = fmaf(v0.w, w0, acc.w);
            acc.x = fmaf(v1.x, w1, acc.x); acc.y = fmaf(v1.y, w1, acc.y);
            acc.z = fmaf(v1.z, w1, acc.z); acc.w = fmaf(v1.w, w1, acc.w);
            acc.x = fmaf(v2.x, w2, acc.x); acc.y = fmaf(v2.y, w2, acc.y);
            acc.z = fmaf(v2.z, w2, acc.z); acc.w = fmaf(v2.w, w2, acc.w);
            acc.x = fmaf(v3.x, w3, acc.x); acc.y = fmaf(v3.y, w3, acc.y);
            acc.z = fmaf(v3.z, w3, acc.z); acc.w = fmaf(v3.w, w3, acc.w);
        }
        for (; e < e1; ++e) {
            int i = g_csrsrc[e];
            float w = g_dinv[i];
            float4 v = hw4[(size_t)i * TX + tx];
            ws += w;
            acc.x = fmaf(v.x, w, acc.x); acc.y = fmaf(v.y, w, acc.y);
            acc.z = fmaf(v.z, w, acc.z); acc.w = fmaf(v.w, w, acc.w);
        }
        float dn = g_dinv[n];
        float sn = g_selfnorm[n];
        float4 hv = hw4[(size_t)n * TX + tx];
        float bx = fmaf(acc.x, dn, hv.x * sn);
        float by = fmaf(acc.y, dn, hv.y * sn);
        float bz = fmaf(acc.z, dn, hv.z * sn);
        float bw = fmaf(acc.w, dn, hv.w * sn);
        if (USE_BN) {
            float sc = fmaf(ws, dn, sn);
            bx = fmaf(al4.x, bx, sc * be4.x);
            by = fmaf(al4.y, by, sc * be4.y);
            bz = fmaf(al4.z, bz, sc * be4.z);
            bw = fmaf(al4.w, bw, sc * be4.w);
        }
        out4[(size_t)n * TX + tx] = make_float4(bx, by, bz, bw);
    }
}

// ---------------- post-aggregation (layer 4): bias+LeakyReLU+BN stats ------
__global__ void agg_post_kernel(const float* __restrict__ hw,
                                const float* __restrict__ bias,
                                float* __restrict__ out) {
    const int DO = 128;
    const int TX = 32, TY = 8, NPB = 32;
    const int tx = threadIdx.x;
    const int ty = threadIdx.y;
    const float4* hw4 = (const float4*)hw;
    float4* out4 = (float4*)out;

    __shared__ float ssum[DO];
    __shared__ float ssq[DO];
    {
        int lin = ty * TX + tx;
        if (lin < DO) { ssum[lin] = 0.f; ssq[lin] = 0.f; }
    }
    __syncthreads();

    float4 b4 = *(const float4*)(bias + 4 * tx);
    int n0 = blockIdx.x * NPB;
    int n1 = min(n0 + NPB, NN);

    float s0 = 0.f, s1 = 0.f, s2 = 0.f, s3 = 0.f;
    float q0 = 0.f, q1 = 0.f, q2 = 0.f, q3 = 0.f;

    for (int n = n0 + ty; n < n1; n += TY) {
        int e0 = g_rowptr[n], e1 = g_rowptr[n + 1];
        float4 acc = make_float4(0.f, 0.f, 0.f, 0.f);
        int e = e0;
        for (; e + 4 <= e1; e += 4) {
            int i0 = g_csrsrc[e],     i1 = g_csrsrc[e + 1];
            int i2 = g_csrsrc[e + 2], i3 = g_csrsrc[e + 3];
            float w0 = g_dinv[i0], w1 = g_dinv[i1];
            float w2 = g_dinv[i2], w3 = g_dinv[i3];
            float4 v0 = hw4[(size_t)i0 * TX + tx];
            float4 v1 = hw4[(size_t)i1 * TX + tx];
            float4 v2 = hw4[(size_t)i2 * TX + tx];
            float4 v3 = hw4[(size_t)i3 * TX + tx];
            acc.x = fmaf(v0.x, w0, acc.x); acc.y = fmaf(v0.y, w0, acc.y);
            acc.z = fmaf(v0.z, w0, acc.z); acc.w = fmaf(v0.w, w0, acc.w);
            acc.x = fmaf(v1.x, w1, acc.x); acc.y = fmaf(v1.y, w1, acc.y);
            acc.z = fmaf(v1.z, w1, acc.z); acc.w = fmaf(v1.w, w1, acc.w);
            acc.x = fmaf(v2.x, w2, acc.x); acc.y = fmaf(v2.y, w2, acc.y);
            acc.z = fmaf(v2.z, w2, acc.z); acc.w = fmaf(v2.w, w2, acc.w);
            acc.x = fmaf(v3.x, w3, acc.x); acc.y = fmaf(v3.y, w3, acc.y);
            acc.z = fmaf(v3.z, w3, acc.z); acc.w = fmaf(v3.w, w3, acc.w);
        }
        for (; e < e1; ++e) {
            int i = g_csrsrc[e];
            float w = g_dinv[i];
            float4 v = hw4[(size_t)i * TX + tx];
            acc.x = fmaf(v.x, w, acc.x); acc.y = fmaf(v.y, w, acc.y);
            acc.z = fmaf(v.z, w, acc.z); acc.w = fmaf(v.w, w, acc.w);
        }
        float dn = g_dinv[n];
        float sn = g_selfnorm[n];
        float4 hv = hw4[(size_t)n * TX + tx];
        float v0 = fmaf(acc.x, dn, hv.x * sn) + b4.x;
        float v1 = fmaf(acc.y, dn, hv.y * sn) + b4.y;
        float v2 = fmaf(acc.z, dn, hv.z * sn) + b4.z;
        float v3 = fmaf(acc.w, dn, hv.w * sn) + b4.w;
        v0 = (v0 > 0.f) ? v0 : NEG_SLOPE * v0;
        v1 = (v1 > 0.f) ? v1 : NEG_SLOPE * v1;
        v2 = (v2 > 0.f) ? v2 : NEG_SLOPE * v2;
        v3 = (v3 > 0.f) ? v3 : NEG_SLOPE * v3;
        out4[(size_t)n * TX + tx] = make_float4(v0, v1, v2, v3);
        s0 += v0; s1 += v1; s2 += v2; s3 += v3;
        q0 = fmaf(v0, v0, q0); q1 = fmaf(v1, v1, q1);
        q2 = fmaf(v2, v2, q2); q3 = fmaf(v3, v3, q3);
    }

    atomicAdd(&ssum[4 * tx + 0], s0);
    atomicAdd(&ssum[4 * tx + 1], s1);
    atomicAdd(&ssum[4 * tx + 2], s2);
    atomicAdd(&ssum[4 * tx + 3], s3);
    atomicAdd(&ssq[4 * tx + 0], q0);
    atomicAdd(&ssq[4 * tx + 1], q1);
    atomicAdd(&ssq[4 * tx + 2], q2);
    atomicAdd(&ssq[4 * tx + 3], q3);
    __syncthreads();
    {
        int lin = ty * TX + tx;
        if (lin < DO) {
            atomicAdd(&g_colsum[lin], ssum[lin]);
            atomicAdd(&g_colsumsq[lin], ssq[lin]);
        }
    }
}

// stats + reset (ready for next layer / next replay)
__global__ void stats_kernel(const float* __restrict__ g,
                             const float* __restrict__ bt, int DO) {
    int t = threadIdx.x;   // 256
    if (t < DO) {
        float mu = g_colsum[t] * (1.0f / NN);
        float var = g_colsumsq[t] * (1.0f / NN) - mu * mu;
        var = fmaxf(var, 0.f);
        float a = g[t] * rsqrtf(var + BN_EPS);
        g_alpha[t] = a;
        g_beta[t] = bt[t] - mu * a;
    }
    g_colsum[t] = 0.f;
    g_colsumsq[t] = 0.f;
}

// Wh/Wl[k,j] = split(alpha[k]*W[k,j]); bconst[j] = sum_k beta[k]*W[k,j]
// (layer 4 only: BN of layer 3 folded into W4)
__global__ void fold_kernel(const float* __restrict__ W, int K, int Nn) {
    int j = blockIdx.x;
    int k = threadIdx.x;   // 256
    __shared__ float red[256];
    float bc = 0.f;
    if (k < K) {
        float w = W[k * Nn + j];
        float wf = g_alpha[k] * w;
        unsigned h = f2tf(wf);
        g_Wh[k * Nn + j] = h;
        g_Wl[k * Nn + j] = f2tf(wf - __uint_as_float(h));
        bc = g_beta[k] * w;
    }
    red[k] = bc;
    __syncthreads();
    for (int off = 128; off > 0; off >>= 1) {
        if (k < off) red[k] += red[k + off];
        __syncthreads();
    }
    if (k == 0) g_bconst[j] = red[0];
}

// ---------------- pooling (counts fused) ----------------
__global__ void pool_kernel(const float* __restrict__ h,
                            const int* __restrict__ batch) {
    const int t = threadIdx.x;   // 128
    const int CH = 128;
    int n0 = blockIdx.x * CH;
    int n1 = min(n0 + CH, NN);
    if (n0 + t < n1) atomicAdd(&g_counts[batch[n0 + t]], 1);
    int cur = batch[n0];
    float acc = 0.f;
    for (int n = n0; n < n1; n++) {
        int gr = batch[n];
        if (gr != cur) {
            atomicAdd(&g_pool[cur * 128 + t], acc);
            acc = 0.f;
            cur = gr;
        }
        acc += h[(size_t)n * 128 + t];
    }
    atomicAdd(&g_pool[cur * 128 + t], acc);
}

__global__ void finalize_kernel(float* __restrict__ out) {
    int gr = blockIdx.x, t = threadIdx.x;
    float c = fmaxf((float)g_counts[gr], 1.0f);
    out[gr * 128 + t] = g_alpha[t] * (g_pool[gr * 128 + t] / c) + g_beta[t];
}

// ---------------- launch ----------------
extern "C" void kernel_launch(void* const* d_in, const int* in_sizes, int n_in,
                              void* d_out, int out_size) {
    const float* x = (const float*)d_in[0];
    const int* ei = (const int*)d_in[1];      // int32 (JAX x64 disabled)
    const int* batch = (const int*)d_in[2];   // int32
    const float* W1 = (const float*)d_in[3];
    const float* b1 = (const float*)d_in[4];
    const float* g1 = (const float*)d_in[5];
    const float* bt1 = (const float*)d_in[6];
    const float* W2 = (const float*)d_in[7];
    const float* b2 = (const float*)d_in[8];
    const float* g2 = (const float*)d_in[9];
    const float* bt2 = (const float*)d_in[10];
    const float* W3 = (const float*)d_in[11];
    const float* b3 = (const float*)d_in[12];
    const float* g3 = (const float*)d_in[13];
    const float* bt3 = (const float*)d_in[14];
    const float* W4 = (const float*)d_in[15];
    const float* b4 = (const float*)d_in[16];
    const float* g4 = (const float*)d_in[17];
    const float* bt4 = (const float*)d_in[18];
    float* out = (float*)d_out;

    float* bufA; cudaGetSymbolAddress((void**)&bufA, g_bufA);
    float* bufB; cudaGetSymbolAddress((void**)&bufB, g_bufB);
    unsigned* Wh; cudaGetSymbolAddress((void**)&Wh, g_Wh);
    unsigned* Wl; cudaGetSymbolAddress((void**)&Wl, g_Wl);
    float* bconst; cudaGetSymbolAddress((void**)&bconst, g_bconst);

    static bool attr_set = false;
    if (!attr_set) {
        cudaFuncSetAttribute(gemm_tf32_kernel<0>,
                             cudaFuncAttributeMaxDynamicSharedMemorySize,
                             GEMM_SMEM_BYTES);
        cudaFuncSetAttribute(gemm_tf32_kernel<1>,
                             cudaFuncAttributeMaxDynamicSharedMemorySize,
                             GEMM_SMEM_BYTES);
        attr_set = true;
    }

    // graph structure (recomputed every call; same work each call)
    zero_misc_kernel<<<(NN + 255) / 256, 256>>>();
    deg_kernel<<<(NE + 255) / 256, 256>>>(ei);
    scan1_kernel<<<NSB, 256>>>();
    scan2_kernel<<<1, 256>>>();
    scan3_kernel<<<(NN + 255) / 256, 256>>>();
    scatter_kernel<<<(NE + 255) / 256, 256>>>(ei);

    dim3 gemm_grid_256(2, NPAD / 128);
    dim3 gemm_grid_128(1, NPAD / 128);
    int agg_grid = (NN + 31) / 32;
    dim3 agg_block_256(64, 4);
    dim3 agg_block_128(32, 8);

    // ---- layer 1: agg-first at 128 feats, fused GEMM epilogue ----
    wsplit_kernel<<<128, 256>>>(W1, 128 * 256);
    agg_pre_kernel<128, 0><<<agg_grid, agg_block_128>>>(x, bufA);
    gemm_tf32_kernel<1><<<gemm_grid_256, 256, GEMM_SMEM_BYTES>>>(
        bufA, Wh, Wl, b1, bufB, 128, 256, NN);
    stats_kernel<<<1, 256>>>(g1, bt1, 256);

    // ---- layer 2: BN applied in agg, raw W2 ----
    wsplit_kernel<<<256, 256>>>(W2, 256 * 256);
    agg_pre_kernel<256, 1><<<agg_grid, agg_block_256>>>(bufB, bufA);
    gemm_tf32_kernel<1><<<gemm_grid_256, 256, GEMM_SMEM_BYTES>>>(
        bufA, Wh, Wl, b2, bufB, 256, 256, NN);
    stats_kernel<<<1, 256>>>(g2, bt2, 256);

    // ---- layer 3 ----
    wsplit_kernel<<<256, 256>>>(W3, 256 * 256);
    agg_pre_kernel<256, 1><<<agg_grid, agg_block_256>>>(bufB, bufA);
    gemm_tf32_kernel<1><<<gemm_grid_256, 256, GEMM_SMEM_BYTES>>>(
        bufA, Wh, Wl, b3, bufB, 256, 256, NN);
    stats_kernel<<<1, 256>>>(g3, bt3, 256);

    // ---- layer 4: BN3 folded into W4, agg-after at 128 feats ----
    fold_kernel<<<128, 256>>>(W4, 256, 128);
    gemm_tf32_kernel<0><<<gemm_grid_128, 256, GEMM_SMEM_BYTES>>>(
        bufB, Wh, Wl, bconst, bufA, 256, 128, NN);
    agg_post_kernel<<<agg_grid, agg_block_128>>>(bufA, b4, bufB);
    stats_kernel<<<1, 256>>>(g4, bt4, 128);

    // ---- pooling ----
    pool_kernel<<<(NN + 127) / 128, 128>>>(bufB, batch);
    finalize_kernel<<<NG, 128>>>(out);
    (void)in_sizes; (void)n_in; (void)out_size;
}

// round 17
// speedup vs baseline: 1.0838x; 1.0838x over previous
#include <cuda_runtime.h>

// Problem constants (fixed by the dataset)
#define NN   50000
#define NE   800000
#define NG   64
#define NPAD 50048            // multiple of 128 for unguarded GEMM
#define NEG_SLOPE 0.01f
#define BN_EPS    1e-5f
#define NSB  196              // scan blocks: ceil(50000/256)

// ---------------- scratch (static __device__, no allocation) ----------------
__device__ __align__(16) float    g_bufA[NPAD * 256];
__device__ __align__(16) float    g_bufB[NPAD * 256];
__device__ __align__(16) unsigned g_Wh[256 * 256];
__device__ __align__(16) unsigned g_Wl[256 * 256];
__device__ __align__(16) int      g_csrsrc[NE];
__device__ __align__(16) int      g_rowptr[NN + 4];
__device__ __align__(16) int      g_deg[NN];
__device__ __align__(16) int      g_fill[NN];
__device__ __align__(16) float    g_dinv[NN];
__device__ __align__(16) float    g_selfnorm[NN];
__device__ __align__(16) int      g_blocksum[256];
__device__ __align__(16) int      g_blockoff[256];
__device__ __align__(16) float    g_colsum[256];
__device__ __align__(16) float    g_colsumsq[256];
__device__ __align__(16) float    g_alpha[256];
__device__ __align__(16) float    g_beta[256];
__device__ __align__(16) float    g_bconst[256];
__device__ __align__(16) float    g_zerovec[256];   // never written -> stays 0
__device__ __align__(16) float    g_pool[NG * 128];
__device__ __align__(16) int      g_counts[NG];

// ---------------- small utility kernels ----------------
__global__ void zero_misc_kernel() {
    int i = blockIdx.x * blockDim.x + threadIdx.x;
    if (i < NN) { g_deg[i] = 0; g_fill[i] = 0; }
    if (i < NG * 128) g_pool[i] = 0.f;
    if (i < NG) g_counts[i] = 0;
    if (blockIdx.x == 0) {               // fused BN-stat zeroing
        g_colsum[threadIdx.x] = 0.f;
        g_colsumsq[threadIdx.x] = 0.f;
    }
}

// edge_index is int32 (JAX x64 disabled downcasts int64 -> int32)
__global__ void deg_kernel(const int* __restrict__ ei) {
    int e = blockIdx.x * blockDim.x + threadIdx.x;
    if (e < NE) atomicAdd(&g_deg[ei[NE + e]], 1);  // dst row
}

// ---------------- parallel 3-stage exclusive scan of g_deg -> g_rowptr -----
__global__ void scan1_kernel() {
    __shared__ int sh[256];
    int b = blockIdx.x, t = threadIdx.x;
    int i = b * 256 + t;
    int v = (i < NN) ? g_deg[i] : 0;
    if (i < NN) {
        float d = (float)(v + 1);
        g_dinv[i] = rsqrtf(d);
        g_selfnorm[i] = 1.0f / d;
    }
    sh[t] = v;
    __syncthreads();
#pragma unroll
    for (int off = 1; off < 256; off <<= 1) {
        int add = (t >= off) ? sh[t - off] : 0;
        __syncthreads();
        sh[t] += add;
        __syncthreads();
    }
    if (i < NN) g_rowptr[i] = sh[t] - v;     // block-local exclusive
    if (t == 255) g_blocksum[b] = sh[255];
}

__global__ void scan2_kernel() {
    __shared__ int sh[256];
    int t = threadIdx.x;
    int v = (t < NSB) ? g_blocksum[t] : 0;
    sh[t] = v;
    __syncthreads();
#pragma unroll
    for (int off = 1; off < 256; off <<= 1) {
        int add = (t >= off) ? sh[t - off] : 0;
        __syncthreads();
        sh[t] += add;
        __syncthreads();
    }
    if (t < NSB) g_blockoff[t] = sh[t] - v;
}

__global__ void scan3_kernel() {
    int i = blockIdx.x * blockDim.x + threadIdx.x;
    if (i < NN) g_rowptr[i] += g_blockoff[i >> 8];
    if (i == 0) g_rowptr[NN] = NE;
}

__global__ void scatter_kernel(const int* __restrict__ ei) {
    int e = blockIdx.x * blockDim.x + threadIdx.x;
    if (e < NE) {
        int s = ei[e];
        int d = ei[NE + e];
        int p = g_rowptr[d] + atomicAdd(&g_fill[d], 1);
        g_csrsrc[p] = s;
    }
}

// ---------------- tf32 helpers ----------------
__device__ __forceinline__ unsigned f2tf(float v) {
    unsigned u;
    asm("cvt.rna.tf32.f32 %0, %1;" : "=r"(u) : "f"(v));
    return u;
}

__device__ __forceinline__ void mma8(float* c, const unsigned* a,
                                     unsigned b0, unsigned b1) {
    asm volatile(
        "mma.sync.aligned.m16n8k8.row.col.f32.tf32.tf32.f32 "
        "{%0,%1,%2,%3}, {%4,%5,%6,%7}, {%8,%9}, {%0,%1,%2,%3};\n"
        : "+f"(c[0]), "+f"(c[1]), "+f"(c[2]), "+f"(c[3])
        : "r"(a[0]), "r"(a[1]), "r"(a[2]), "r"(a[3]), "r"(b0), "r"(b1));
}

__device__ __forceinline__ void cp16(unsigned smem_addr, const void* gptr,
                                     unsigned srcbytes) {
    asm volatile("cp.async.ca.shared.global [%0], [%1], 16, %2;\n"
                 :: "r"(smem_addr), "l"(gptr), "r"(srcbytes));
}

// split W1 into (hi,lo) tf32 globals
__global__ void w1split_kernel(const float* __restrict__ W1) {
    int i = blockIdx.x * 256 + threadIdx.x;
    if (i < 128 * 256) {
        float w = W1[i];
        unsigned h = f2tf(w);
        g_Wh[i] = h;
        g_Wl[i] = f2tf(w - __uint_as_float(h));
    }
}

// ---------------- 3xTF32 tensor-core GEMM (cp.async double-buffered) -------
// C[M,Nn] = A[M,K] @ W[K,Nn] + bconst. W pre-split to (hi,lo) in global.
// A copied raw fp32 via cp.async ([m][k] stride-20 smem), split at fragment
// load. Block 128x128, 8 warps (2x4), warp tile 64x32, BK=16, 2 stages.
#define ASTRIDE 20                    // floats; 80B rows, conflict-free
#define BSTRIDE 136                   // words; 136%32==8 -> conflict-free
#define A_WORDS (128 * ASTRIDE)       // 2560
#define B_WORDS (16 * BSTRIDE)        // 2176
#define GEMM_SMEM_BYTES ((2 * A_WORDS + 4 * B_WORDS) * 4)   // 55296

__global__ __launch_bounds__(256, 2)
void gemm_tf32_kernel(const float* __restrict__ A,
                      const unsigned* __restrict__ Wh,
                      const unsigned* __restrict__ Wl,
                      const float* __restrict__ bconst, float* __restrict__ C,
                      int K, int Nn, int nrowsA) {
    extern __shared__ unsigned smem[];
    float* Af = (float*)smem;                      // [2][A_WORDS]
    unsigned* Bh = smem + 2 * A_WORDS;             // [2][B_WORDS]
    unsigned* Bl = Bh + 2 * B_WORDS;               // [2][B_WORDS]

    const int tid = threadIdx.x;
    const int lane = tid & 31;
    const int w = tid >> 5;
    const int wm = w >> 2;            // 0..1
    const int wn = w & 3;             // 0..3
    const int q = lane >> 2;          // 0..7
    const int r4 = lane & 3;          // 0..3

    const int rowbase = blockIdx.y * 128;
    const float* Ab = A + (size_t)rowbase * K;
    const int colbase = blockIdx.x * 128;
    float* Cb = C + (size_t)rowbase * Nn + colbase;

    unsigned af_base = (unsigned)__cvta_generic_to_shared(Af);
    unsigned bh_base = (unsigned)__cvta_generic_to_shared(Bh);
    unsigned bl_base = (unsigned)__cvta_generic_to_shared(Bl);

    auto issue = [&](int k0, int s) {
#pragma unroll
        for (int i = 0; i < 2; i++) {
            int idx = i * 256 + tid;
            int m = idx >> 2, ch = idx & 3;
            unsigned ok = (rowbase + m < nrowsA) ? 16u : 0u;
            const float* src = Ab + (size_t)m * K + k0 + ch * 4;
            cp16(af_base + (s * A_WORDS + m * ASTRIDE + ch * 4) * 4, src, ok);
        }
#pragma unroll
        for (int i = 0; i < 2; i++) {
            int idx = i * 256 + tid;
            int kk = idx >> 5, c = idx & 31;
            size_t goff = (size_t)(k0 + kk) * Nn + colbase + c * 4;
            unsigned soff = (s * B_WORDS + kk * BSTRIDE + c * 4) * 4;
            cp16(bh_base + soff, Wh + goff, 16u);
            cp16(bl_base + soff, Wl + goff, 16u);
        }
        asm volatile("cp.async.commit_group;\n" ::);
    };

    float acc[4][4][4];
#pragma unroll
    for (int mi = 0; mi < 4; mi++)
#pragma unroll
        for (int ni = 0; ni < 4; ni++)
#pragma unroll
            for (int rr = 0; rr < 4; rr++) acc[mi][ni][rr] = 0.f;

    const int T = K / 16;
    issue(0, 0);
    for (int t = 0; t < T; ++t) {
        const int p = t & 1;
        if (t + 1 < T) {
            issue((t + 1) * 16, (t + 1) & 1);
            asm volatile("cp.async.wait_group 1;\n" ::);
        } else {
            asm volatile("cp.async.wait_group 0;\n" ::);
        }
        __syncthreads();

        const float* Ap = Af + p * A_WORDS;
        const unsigned* Bhp = Bh + p * B_WORDS;
        const unsigned* Blp = Bl + p * B_WORDS;
#pragma unroll
        for (int ks = 0; ks < 2; ks++) {
            const int kk0 = ks * 8 + r4;
            unsigned ah[4][4], al[4][4];
#pragma unroll
            for (int mi = 0; mi < 4; mi++) {
                int m0 = wm * 64 + mi * 16 + q;
                float f0 = Ap[m0 * ASTRIDE + kk0];
                float f1 = Ap[(m0 + 8) * ASTRIDE + kk0];
                float f2 = Ap[m0 * ASTRIDE + kk0 + 4];
                float f3 = Ap[(m0 + 8) * ASTRIDE + kk0 + 4];
                ah[mi][0] = f2tf(f0); al[mi][0] = f2tf(f0 - __uint_as_float(ah[mi][0]));
                ah[mi][1] = f2tf(f1); al[mi][1] = f2tf(f1 - __uint_as_float(ah[mi][1]));
                ah[mi][2] = f2tf(f2); al[mi][2] = f2tf(f2 - __uint_as_float(ah[mi][2]));
                ah[mi][3] = f2tf(f3); al[mi][3] = f2tf(f3 - __uint_as_float(ah[mi][3]));
            }
#pragma unroll
            for (int ni = 0; ni < 4; ni++) {
                int n0b = wn * 32 + ni * 8 + q;
                unsigned bh0 = Bhp[kk0 * BSTRIDE + n0b];
                unsigned bh1 = Bhp[(kk0 + 4) * BSTRIDE + n0b];
                unsigned bl0 = Blp[kk0 * BSTRIDE + n0b];
                unsigned bl1 = Blp[(kk0 + 4) * BSTRIDE + n0b];
#pragma unroll
                for (int mi = 0; mi < 4; mi++) {
                    mma8(acc[mi][ni], ah[mi], bh0, bh1);  // hi*hi
                    mma8(acc[mi][ni], al[mi], bh0, bh1);  // lo*hi
                    mma8(acc[mi][ni], ah[mi], bl0, bl1);  // hi*lo
                }
            }
        }
        __syncthreads();
    }

    // ---- epilogue: add bconst, store float2 pairs ----
#pragma unroll
    for (int ni = 0; ni < 4; ni++) {
        int ncol = wn * 32 + ni * 8 + 2 * r4;
        float bcx = bconst[colbase + ncol];
        float bcy = bconst[colbase + ncol + 1];
#pragma unroll
        for (int mi = 0; mi < 4; mi++) {
            int row0 = wm * 64 + mi * 16 + q;
            float2 v0 = make_float2(acc[mi][ni][0] + bcx, acc[mi][ni][1] + bcy);
            float2 v1 = make_float2(acc[mi][ni][2] + bcx, acc[mi][ni][3] + bcy);
            *(float2*)(Cb + (size_t)row0 * Nn + ncol) = v0;
            *(float2*)(Cb + (size_t)(row0 + 8) * Nn + ncol) = v1;
        }
    }
}

// ---------------- aggregation + bias + LeakyReLU + BN-stat partials --------
// float4-vectorized; edge weight = dinv[src], scaled by dinv[dst] per row.
template <int DO>
__global__ void agg_kernel(const float* __restrict__ hw,
                           const float* __restrict__ bias,
                           float* __restrict__ out) {
    const int TX = DO / 4;            // threads along features (64 or 32)
    const int TY = 256 / TX;          // node lanes (4 or 8)
    const int NPB = 32;
    const int tx = threadIdx.x;       // feature group
    const int ty = threadIdx.y;       // node lane
    const float4* hw4 = (const float4*)hw;
    float4* out4 = (float4*)out;

    __shared__ float ssum[DO];
    __shared__ float ssq[DO];
    {
        int lin = ty * TX + tx;
        if (lin < DO) { ssum[lin] = 0.f; ssq[lin] = 0.f; }
    }
    __syncthreads();

    float4 b4 = *(const float4*)(bias + 4 * tx);
    int n0 = blockIdx.x * NPB;
    int n1 = min(n0 + NPB, NN);

    float s0 = 0.f, s1 = 0.f, s2 = 0.f, s3 = 0.f;
    float q0 = 0.f, q1 = 0.f, q2 = 0.f, q3 = 0.f;

    for (int n = n0 + ty; n < n1; n += TY) {
        int e0 = g_rowptr[n], e1 = g_rowptr[n + 1];
        float4 acc = make_float4(0.f, 0.f, 0.f, 0.f);
        int e = e0;
        for (; e + 4 <= e1; e += 4) {
            int i0 = g_csrsrc[e],     i1 = g_csrsrc[e + 1];
            int i2 = g_csrsrc[e + 2], i3 = g_csrsrc[e + 3];
            float w0 = g_dinv[i0], w1 = g_dinv[i1];
            float w2 = g_dinv[i2], w3 = g_dinv[i3];
            float4 v0 = hw4[(size_t)i0 * TX + tx];
            float4 v1 = hw4[(size_t)i1 * TX + tx];
            float4 v2 = hw4[(size_t)i2 * TX + tx];
            float4 v3 = hw4[(size_t)i3 * TX + tx];
            acc.x = fmaf(v0.x, w0, acc.x); acc.y = fmaf(v0.y, w0, acc.y);
            acc.z = fmaf(v0.z, w0, acc.z); acc.w = fmaf(v0.w, w0, acc.w);
            acc.x = fmaf(v1.x, w1, acc.x); acc.y = fmaf(v1.y, w1, acc.y);
            acc.z = fmaf(v1.z, w1, acc.z); acc.w = fmaf(v1.w, w1, acc.w);
            acc.x = fmaf(v2.x, w2, acc.x); acc.y = fmaf(v2.y, w2, acc.y);
            acc.z = fmaf(v2.z, w2, acc.z); acc.w = fmaf(v2.w, w2, acc.w);
            acc.x = fmaf(v3.x, w3, acc.x); acc.y = fmaf(v3.y, w3, acc.y);
            acc.z = fmaf(v3.z, w3, acc.z); acc.w = fmaf(v3.w, w3, acc.w);
        }
        for (; e < e1; ++e) {
            int i = g_csrsrc[e];
            float w = g_dinv[i];
            float4 v = hw4[(size_t)i * TX + tx];
            acc.x = fmaf(v.x, w, acc.x); acc.y = fmaf(v.y, w, acc.y);
            acc.z = fmaf(v.z, w, acc.z); acc.w = fmaf(v.w, w, acc.w);
        }
        float dn = g_dinv[n];
        float sn = g_selfnorm[n];
        float4 hv = hw4[(size_t)n * TX + tx];
        float v0 = fmaf(acc.x, dn, hv.x * sn) + b4.x;
        float v1 = fmaf(acc.y, dn, hv.y * sn) + b4.y;
        float v2 = fmaf(acc.z, dn, hv.z * sn) + b4.z;
        float v3 = fmaf(acc.w, dn, hv.w * sn) + b4.w;
        v0 = (v0 > 0.f) ? v0 : NEG_SLOPE * v0;
        v1 = (v1 > 0.f) ? v1 : NEG_SLOPE * v1;
        v2 = (v2 > 0.f) ? v2 : NEG_SLOPE * v2;
        v3 = (v3 > 0.f) ? v3 : NEG_SLOPE * v3;
        out4[(size_t)n * TX + tx] = make_float4(v0, v1, v2, v3);
        s0 += v0; s1 += v1; s2 += v2; s3 += v3;
        q0 = fmaf(v0, v0, q0); q1 = fmaf(v1, v1, q1);
        q2 = fmaf(v2, v2, q2); q3 = fmaf(v3, v3, q3);
    }

    atomicAdd(&ssum[4 * tx + 0], s0);
    atomicAdd(&ssum[4 * tx + 1], s1);
    atomicAdd(&ssum[4 * tx + 2], s2);
    atomicAdd(&ssum[4 * tx + 3], s3);
    atomicAdd(&ssq[4 * tx + 0], q0);
    atomicAdd(&ssq[4 * tx + 1], q1);
    atomicAdd(&ssq[4 * tx + 2], q2);
    atomicAdd(&ssq[4 * tx + 3], q3);
    __syncthreads();
    {
        int lin = ty * TX + tx;
        if (lin < DO) {
            atomicAdd(&g_colsum[lin], ssum[lin]);
            atomicAdd(&g_colsumsq[lin], ssq[lin]);
        }
    }
}

// stats + reset (ready for next layer / next replay)
__global__ void stats_kernel(const float* __restrict__ g,
                             const float* __restrict__ bt, int DO) {
    int t = threadIdx.x;   // 256
    if (t < DO) {
        float mu = g_colsum[t] * (1.0f / NN);
        float var = g_colsumsq[t] * (1.0f / NN) - mu * mu;
        var = fmaxf(var, 0.f);
        float a = g[t] * rsqrtf(var + BN_EPS);
        g_alpha[t] = a;
        g_beta[t] = bt[t] - mu * a;
    }
    g_colsum[t] = 0.f;
    g_colsumsq[t] = 0.f;
}

// Wh/Wl[k,j] = split(alpha[k]*W[k,j]); bconst[j] = sum_k beta[k]*W[k,j]
__global__ void fold_kernel(const float* __restrict__ W, int K, int Nn) {
    int j = blockIdx.x;
    int k = threadIdx.x;   // 256
    __shared__ float red[256];
    float bc = 0.f;
    if (k < K) {
        float w = W[k * Nn + j];
        float wf = g_alpha[k] * w;
        unsigned h = f2tf(wf);
        g_Wh[k * Nn + j] = h;
        g_Wl[k * Nn + j] = f2tf(wf - __uint_as_float(h));
        bc = g_beta[k] * w;
    }
    red[k] = bc;
    __syncthreads();
    for (int off = 128; off > 0; off >>= 1) {
        if (k < off) red[k] += red[k + off];
        __syncthreads();
    }
    if (k == 0) g_bconst[j] = red[0];
}

// ---------------- pooling (counts fused) ----------------
__global__ void pool_kernel(const float* __restrict__ h,
                            const int* __restrict__ batch) {
    const int t = threadIdx.x;   // 128
    const int CH = 128;
    int n0 = blockIdx.x * CH;
    int n1 = min(n0 + CH, NN);
    if (n0 + t < n1) atomicAdd(&g_counts[batch[n0 + t]], 1);
    int cur = batch[n0];
    float acc = 0.f;
    for (int n = n0; n < n1; n++) {
        int gr = batch[n];
        if (gr != cur) {
            atomicAdd(&g_pool[cur * 128 + t], acc);
            acc = 0.f;
            cur = gr;
        }
        acc += h[(size_t)n * 128 + t];
    }
    atomicAdd(&g_pool[cur * 128 + t], acc);
}

__global__ void finalize_kernel(float* __restrict__ out) {
    int gr = blockIdx.x, t = threadIdx.x;
    float c = fmaxf((float)g_counts[gr], 1.0f);
    out[gr * 128 + t] = g_alpha[t] * (g_pool[gr * 128 + t] / c) + g_beta[t];
}

// ---------------- launch ----------------
extern "C" void kernel_launch(void* const* d_in, const int* in_sizes, int n_in,
                              void* d_out, int out_size) {
    const float* x = (const float*)d_in[0];
    const int* ei = (const int*)d_in[1];      // int32 (JAX x64 disabled)
    const int* batch = (const int*)d_in[2];   // int32
    const float* W1 = (const float*)d_in[3];
    const float* b1 = (const float*)d_in[4];
    const float* g1 = (const float*)d_in[5];
    const float* bt1 = (const float*)d_in[6];
    const float* W2 = (const float*)d_in[7];
    const float* b2 = (const float*)d_in[8];
    const float* g2 = (const float*)d_in[9];
    const float* bt2 = (const float*)d_in[10];
    const float* W3 = (const float*)d_in[11];
    const float* b3 = (const float*)d_in[12];
    const float* g3 = (const float*)d_in[13];
    const float* bt3 = (const float*)d_in[14];
    const float* W4 = (const float*)d_in[15];
    const float* b4 = (const float*)d_in[16];
    const float* g4 = (const float*)d_in[17];
    const float* bt4 = (const float*)d_in[18];
    float* out = (float*)d_out;

    float* bufA; cudaGetSymbolAddress((void**)&bufA, g_bufA);
    float* bufB; cudaGetSymbolAddress((void**)&bufB, g_bufB);
    unsigned* Wh; cudaGetSymbolAddress((void**)&Wh, g_Wh);
    unsigned* Wl; cudaGetSymbolAddress((void**)&Wl, g_Wl);
    float* bconst; cudaGetSymbolAddress((void**)&bconst, g_bconst);
    float* zerovec; cudaGetSymbolAddress((void**)&zerovec, g_zerovec);

    static bool init_done = false;
    static cudaStream_t s2 = 0;
    static cudaEvent_t evFork = 0, evJoin = 0;
    if (!init_done) {
        cudaFuncSetAttribute(gemm_tf32_kernel,
                             cudaFuncAttributeMaxDynamicSharedMemorySize,
                             GEMM_SMEM_BYTES);
        cudaStreamCreateWithFlags(&s2, cudaStreamNonBlocking);
        cudaEventCreateWithFlags(&evFork, cudaEventDisableTiming);
        cudaEventCreateWithFlags(&evJoin, cudaEventDisableTiming);
        init_done = true;
    }

    // ---- fork: graph build on s2, concurrent with w1split + layer-1 GEMM --
    cudaEventRecord(evFork, 0);
    cudaStreamWaitEvent(s2, evFork, 0);

    zero_misc_kernel<<<(NN + 255) / 256, 256, 0, s2>>>();
    deg_kernel<<<(NE + 255) / 256, 256, 0, s2>>>(ei);
    scan1_kernel<<<NSB, 256, 0, s2>>>();
    scan2_kernel<<<1, 256, 0, s2>>>();
    scan3_kernel<<<(NN + 255) / 256, 256, 0, s2>>>();
    scatter_kernel<<<(NE + 255) / 256, 256, 0, s2>>>(ei);
    cudaEventRecord(evJoin, s2);

    dim3 gemm_grid_256(2, NPAD / 128);
    dim3 gemm_grid_128(1, NPAD / 128);
    int agg_grid = (NN + 31) / 32;
    dim3 agg_block_256(64, 4);
    dim3 agg_block_128(32, 8);

    // ---- layer 1 GEMM (independent of graph; reads x + W1) ----
    w1split_kernel<<<128, 256>>>(W1);
    gemm_tf32_kernel<<<gemm_grid_256, 256, GEMM_SMEM_BYTES>>>(
        x, Wh, Wl, zerovec, bufB, 128, 256, NN);

    // ---- join: aggregation needs the CSR ----
    cudaStreamWaitEvent(0, evJoin, 0);

    agg_kernel<256><<<agg_grid, agg_block_256>>>(bufB, b1, bufA);
    stats_kernel<<<1, 256>>>(g1, bt1, 256);
    fold_kernel<<<256, 256>>>(W2, 256, 256);

    // ---- layer 2: 256 -> 256 ----
    gemm_tf32_kernel<<<gemm_grid_256, 256, GEMM_SMEM_BYTES>>>(
        bufA, Wh, Wl, bconst, bufB, 256, 256, NPAD);
    agg_kernel<256><<<agg_grid, agg_block_256>>>(bufB, b2, bufA);
    stats_kernel<<<1, 256>>>(g2, bt2, 256);
    fold_kernel<<<256, 256>>>(W3, 256, 256);

    // ---- layer 3: 256 -> 256 ----
    gemm_tf32_kernel<<<gemm_grid_256, 256, GEMM_SMEM_BYTES>>>(
        bufA, Wh, Wl, bconst, bufB, 256, 256, NPAD);
    agg_kernel<256><<<agg_grid, agg_block_256>>>(bufB, b3, bufA);
    stats_kernel<<<1, 256>>>(g3, bt3, 256);
    fold_kernel<<<128, 256>>>(W4, 256, 128);

    // ---- layer 4: 256 -> 128 ----
    gemm_tf32_kernel<<<gemm_grid_128, 256, GEMM_SMEM_BYTES>>>(
        bufA, Wh, Wl, bconst, bufB, 256, 128, NPAD);
    agg_kernel<128><<<agg_grid, agg_block_128>>>(bufB, b4, bufA);
    stats_kernel<<<1, 256>>>(g4, bt4, 128);

    // ---- pooling ----
    pool_kernel<<<(NN + 127) / 128, 128>>>(bufA, batch);
    finalize_kernel<<<NG, 128>>>(out);
    (void)in_sizes; (void)n_in; (void)out_size;
}